// round 1
// baseline (speedup 1.0000x reference)
#include <cuda_runtime.h>

#define NB 16
#define NV 10000
#define NR 8
#define NC 64
#define NU 64

#define ROWS 256           // output rows per CTA
#define NTHREADS 256
#define APAD 68            // floats per A row (64 + 4 pad, 16B-aligned, conflict-free)

#define SA_FLOATS (ROWS * APAD)   // 17408
#define SK_FLOATS (NC * NU)       // 4096
#define SMEM_BYTES ((SA_FLOATS + SK_FLOATS) * 4)   // 86016 B

// packed fp32x2 FMA (sm_103a FFMA2 — only reachable via PTX)
__device__ __forceinline__ unsigned long long fma2(unsigned long long a,
                                                   unsigned long long b,
                                                   unsigned long long c) {
    unsigned long long d;
    asm("fma.rn.f32x2 %0, %1, %2, %3;" : "=l"(d) : "l"(a), "l"(b), "l"(c));
    return d;
}
__device__ __forceinline__ unsigned long long bcast2(float x) {
    unsigned long long d;
    asm("mov.b64 %0, {%1, %1};" : "=l"(d) : "f"(x));
    return d;
}
__device__ __forceinline__ float2 unpack2(unsigned long long v) {
    float2 f;
    asm("mov.b64 {%0, %1}, %2;" : "=f"(f.x), "=f"(f.y) : "l"(v));
    return f;
}

__global__ void __launch_bounds__(NTHREADS, 2)
graphconv_kernel(const float* __restrict__ nodes,
                 const int*   __restrict__ mapping,
                 const float* __restrict__ kern,
                 const float* __restrict__ bias,
                 float*       __restrict__ out)
{
    extern __shared__ float smem[];
    float* sA = smem;               // [ROWS][APAD]
    float* sK = smem + SA_FLOATS;   // [NC][NU]

    const int tid = threadIdx.x;
    const int tx  = tid & 7;        // u-group: u = tx*8 .. tx*8+7
    const int ty  = tid >> 3;       // 0..31: rows ty + 32*i, i=0..7
    const int row0 = blockIdx.x * ROWS;

    // ---- gather assignment: 8 lanes per row, 8 passes of 32 rows ----
    const int ql  = tid & 7;        // lane within row (2 float4 each)
    const int grr = tid >> 3;       // 0..31 row within pass

    // precompute b*V for each pass (division hoisted out of the region loop)
    int bV[8];
#pragma unroll
    for (int p = 0; p < 8; ++p) {
        int grow = row0 + p * 32 + grr;
        bV[p] = (grow / NV) * NV;
    }

    unsigned long long acc[8][4];
#pragma unroll
    for (int i = 0; i < 8; ++i)
#pragma unroll
        for (int p = 0; p < 4; ++p) acc[i][p] = 0ULL;

    for (int r = 0; r < NR; ++r) {
        __syncthreads();   // previous-region compute done before overwriting SMEM

        // ---- load K_r [64][64] into SMEM ----
        {
            const float4* kg = (const float4*)(kern + (size_t)r * NC * NU);
            float4* ks = (float4*)sK;
#pragma unroll
            for (int i = 0; i < (NC * NU / 4) / NTHREADS; ++i)
                ks[tid + i * NTHREADS] = kg[tid + i * NTHREADS];
        }

        // ---- gather A_r [256][64] (padded to APAD) ----
#pragma unroll
        for (int p = 0; p < 8; ++p) {
            int lrow = p * 32 + grr;
            int grow = row0 + lrow;
            int m = __ldg(mapping + (size_t)grow * NR + r);
            float4 v0, v1;
            if (m >= 0) {
                const float4* src =
                    (const float4*)(nodes + ((size_t)(bV[p] + m) << 6)) + (ql << 1);
                v0 = src[0];
                v1 = src[1];
            } else {
                v0 = make_float4(0.f, 0.f, 0.f, 0.f);
                v1 = v0;
            }
            float4* dst = (float4*)(sA + lrow * APAD) + (ql << 1);
            dst[0] = v0;
            dst[1] = v1;
        }
        __syncthreads();

        // ---- accumulate: per k, 32 FFMA2 + 8 LDS.32 + 2 LDS.128 per thread ----
#pragma unroll 2
        for (int k = 0; k < NC; ++k) {
            const ulonglong2* kp = (const ulonglong2*)(sK + k * NU + tx * 8);
            ulonglong2 ka = kp[0];
            ulonglong2 kb = kp[1];
#pragma unroll
            for (int i = 0; i < 8; ++i) {
                unsigned long long a2 = bcast2(sA[(ty + 32 * i) * APAD + k]);
                acc[i][0] = fma2(a2, ka.x, acc[i][0]);
                acc[i][1] = fma2(a2, ka.y, acc[i][1]);
                acc[i][2] = fma2(a2, kb.x, acc[i][2]);
                acc[i][3] = fma2(a2, kb.y, acc[i][3]);
            }
        }
    }

    // ---- epilogue: bias + relu, vectorized stores ----
    const float4* bg = (const float4*)bias;
    float4 b0 = bg[tx * 2];
    float4 b1 = bg[tx * 2 + 1];

#pragma unroll
    for (int i = 0; i < 8; ++i) {
        int orow = row0 + ty + 32 * i;
        float2 f0 = unpack2(acc[i][0]);
        float2 f1 = unpack2(acc[i][1]);
        float2 f2 = unpack2(acc[i][2]);
        float2 f3 = unpack2(acc[i][3]);
        float4 o0, o1;
        o0.x = fmaxf(f0.x + b0.x, 0.f);
        o0.y = fmaxf(f0.y + b0.y, 0.f);
        o0.z = fmaxf(f1.x + b0.z, 0.f);
        o0.w = fmaxf(f1.y + b0.w, 0.f);
        o1.x = fmaxf(f2.x + b1.x, 0.f);
        o1.y = fmaxf(f2.y + b1.y, 0.f);
        o1.z = fmaxf(f3.x + b1.z, 0.f);
        o1.w = fmaxf(f3.y + b1.w, 0.f);
        float4* op = (float4*)(out + (size_t)orow * NU + tx * 8);
        op[0] = o0;
        op[1] = o1;
    }
}

extern "C" void kernel_launch(void* const* d_in, const int* in_sizes, int n_in,
                              void* d_out, int out_size) {
    (void)in_sizes; (void)n_in; (void)out_size;
    const float* nodes   = (const float*)d_in[0];
    const int*   mapping = (const int*)d_in[1];
    const float* kern    = (const float*)d_in[2];
    const float* bias    = (const float*)d_in[3];
    float*       out     = (float*)d_out;

    cudaFuncSetAttribute(graphconv_kernel,
                         cudaFuncAttributeMaxDynamicSharedMemorySize, SMEM_BYTES);

    int grid = (NB * NV) / ROWS;   // 160000 / 256 = 625
    graphconv_kernel<<<grid, NTHREADS, SMEM_BYTES>>>(nodes, mapping, kern, bias, out);
}